// round 7
// baseline (speedup 1.0000x reference)
#include <cuda_runtime.h>
#include <cstdint>

// Problem constants
#define B_      2
#define L_      2048
#define D_      1024
#define H_      16
#define HD_     64
#define CHUNK_  128
#define M_ROWS  (B_ * L_)          // 4096
#define QKV_N   (3 * D_)           // 3072

// Scratch (device globals — no allocation allowed)
__device__ __align__(16) float g_q[(size_t)B_ * H_ * L_ * HD_];     // [bh][l][perm16(d)]
__device__ __align__(16) float g_k[(size_t)B_ * H_ * L_ * HD_];     // [bh][l][perm16(d)]
__device__ __align__(16) float g_v[(size_t)B_ * H_ * HD_ * L_];     // [bh][d][vperm16(l)]
__device__ __align__(16) float g_ctx[(size_t)B_ * L_ * D_];         // [m][perm16(c)]
__device__ __align__(16) float g_xr[(size_t)M_ROWS * D_];           // [m][perm16(k)]
__device__ __align__(16) float g_wqkvr[(size_t)QKV_N * D_];         // [n][perm16(k)]
__device__ __align__(16) float g_woutr[(size_t)D_ * D_];            // [n][perm16(k)]

// ===========================================================================
// Helpers
// ===========================================================================
__device__ __forceinline__ uint32_t smem_u32(const void* p) {
    uint32_t a;
    asm("{ .reg .u64 t; cvta.to.shared.u64 t, %1; cvt.u32.u64 %0, t; }" : "=r"(a) : "l"(p));
    return a;
}
__device__ __forceinline__ uint32_t f2tf(float x) {
    uint32_t r;
    asm("cvt.rna.tf32.f32 %0, %1;" : "=r"(r) : "f"(x));
    return r;
}
__device__ __forceinline__ float f2tff(float x) { return __uint_as_float(f2tf(x)); }

// 16-wide fragment permutation for the mma K-dim:
// orig k = g8*8 + h*4 + t  ->  pos = t*4 + g8*2 + h
// Thread tq then LDS.128s pos tq*4..tq*4+3 = k { tq, tq+4, 8+tq, 12+tq }:
// fragment regs for TWO adjacent 8-groups in one load.
__device__ __forceinline__ int perm16(int i) {
    return (i & ~15) | ((i & 3) << 2) | (((i >> 3) & 1) << 1) | ((i >> 2) & 1);
}
// V-key interleave compatible with the C-frag relabel (slot tq <-> key 2tq):
// orig key k = g8*8 + t*2 + p -> pos = t*4 + g8*2 + p
__device__ __forceinline__ int vperm16(int k) {
    return (k & ~15) | (((k & 7) >> 1) << 2) | (((k >> 3) & 1) << 1) | (k & 1);
}

// m16n8k8 tf32 mma: D = A*B + D  (A row-major, B col-major)
__device__ __forceinline__ void mma8(float* c, const uint32_t* a, const uint32_t* b) {
    asm volatile(
        "mma.sync.aligned.m16n8k8.row.col.f32.tf32.tf32.f32 "
        "{%0,%1,%2,%3}, {%4,%5,%6,%7}, {%8,%9}, {%0,%1,%2,%3};"
        : "+f"(c[0]), "+f"(c[1]), "+f"(c[2]), "+f"(c[3])
        : "r"(a[0]), "r"(a[1]), "r"(a[2]), "r"(a[3]), "r"(b[0]), "r"(b[1]));
}

__device__ __forceinline__ void cp16(uint32_t dst, const void* src) {
    asm volatile("cp.async.cg.shared.global [%0], [%1], 16;" :: "r"(dst), "l"(src));
}
#define CP_COMMIT() asm volatile("cp.async.commit_group;" ::: "memory")
#define CP_WAIT0()  asm volatile("cp.async.wait_group 0;" ::: "memory")
#define CP_WAIT1()  asm volatile("cp.async.wait_group 1;" ::: "memory")

// ===========================================================================
// Prep kernels
// ===========================================================================
// round to tf32 + 16-perm (each thread owns one 16-group)
__global__ __launch_bounds__(256) void roundperm_kernel(
    const float4* __restrict__ in, float4* __restrict__ out, int n16)
{
    const int i = blockIdx.x * blockDim.x + threadIdx.x;
    if (i < n16) {
        const float4 v0 = in[4 * i], v1 = in[4 * i + 1];
        const float4 v2 = in[4 * i + 2], v3 = in[4 * i + 3];
        const float f[16] = { v0.x, v0.y, v0.z, v0.w, v1.x, v1.y, v1.z, v1.w,
                              v2.x, v2.y, v2.z, v2.w, v3.x, v3.y, v3.z, v3.w };
#pragma unroll
        for (int j = 0; j < 4; j++)
            out[4 * i + j] = make_float4(f2tff(f[j]), f2tff(f[j + 4]),
                                         f2tff(f[j + 8]), f2tff(f[j + 12]));
    }
}

// W[K][N] -> Wt[N][perm16(K)] with tf32 rounding (tiled transpose)
__global__ __launch_bounds__(256) void transperm_kernel(
    const float* __restrict__ in, float* __restrict__ out, int K, int N)
{
    __shared__ float tile[32][33];
    const int k0 = blockIdx.y * 32, n0 = blockIdx.x * 32;
    const int tx = threadIdx.x, ty = threadIdx.y;    // 32 x 8
#pragma unroll
    for (int i = 0; i < 4; i++)
        tile[ty + 8 * i][tx] = in[(size_t)(k0 + ty + 8 * i) * N + n0 + tx];
    __syncthreads();
    const int kp = k0 + perm16(tx);
#pragma unroll
    for (int i = 0; i < 4; i++)
        out[(size_t)(n0 + ty + 8 * i) * K + kp] = f2tff(tile[tx][ty + 8 * i]);
}

// ===========================================================================
// tf32 mma GEMM: C[M,N] = A[M,K] @ W[K,N] + bias
// A: [M][perm16(K)], Bt: [N][perm16(K)]. 128x128 CTA, BK=32, 2-stage.
// smem stride 48 floats (192 B == 64 mod 128) -> LDS.128 conflict-free.
// ===========================================================================
#define GS 48
#define GSTAGE_B (128 * GS * 4)     // 24576 bytes
#define G_BOFF   (2 * GSTAGE_B)
#define GEMM_SMEM (4 * GSTAGE_B)    // 98304 bytes

__device__ __forceinline__ void gemm_prefetch(
    uint32_t sb, int s, const float* A, const float* Bt,
    int K, int bm, int bn, int k0, int tid)
{
    const uint32_t a_st = sb + (uint32_t)s * GSTAGE_B;
    const uint32_t b_st = sb + G_BOFF + (uint32_t)s * GSTAGE_B;
#pragma unroll
    for (int i = 0; i < 4; i++) {
        const int idx = tid + i * 256;
        const int r = idx >> 3, c = idx & 7;
        cp16(a_st + r * (GS * 4) + c * 16, A + (size_t)(bm + r) * K + k0 + c * 4);
    }
#pragma unroll
    for (int i = 0; i < 4; i++) {
        const int idx = tid + i * 256;
        const int r = idx >> 3, c = idx & 7;
        cp16(b_st + r * (GS * 4) + c * 16, Bt + (size_t)(bn + r) * K + k0 + c * 4);
    }
}

__global__ __launch_bounds__(256, 2) void gemm_mma_kernel(
    const float* __restrict__ A, const float* __restrict__ Bt,
    const float* __restrict__ bias, float* __restrict__ C,
    int M, int N, int K, int qkv_mode)
{
    extern __shared__ __align__(16) char sm[];
    const uint32_t sb = smem_u32(sm);
    const int tid = threadIdx.x, wid = tid >> 5, lane = tid & 31;
    const int g = lane >> 2, tq = lane & 3;
    const int bm = blockIdx.y * 128, bn = blockIdx.x * 128;
    const int wm = (wid >> 2) * 64, wn = (wid & 3) * 32;

    float c[4][4][4];
#pragma unroll
    for (int mt = 0; mt < 4; mt++)
#pragma unroll
        for (int nt = 0; nt < 4; nt++)
#pragma unroll
            for (int i = 0; i < 4; i++) c[mt][nt][i] = 0.f;

    const int KT = K >> 5;
    gemm_prefetch(sb, 0, A, Bt, K, bm, bn, 0, tid);  CP_COMMIT();
    gemm_prefetch(sb, 1, A, Bt, K, bm, bn, 32, tid); CP_COMMIT();

    for (int t = 0; t < KT; t++) {
        CP_WAIT1();
        __syncthreads();
        const int s = t & 1;
        {
            const float* As = (const float*)(sm + (size_t)s * GSTAGE_B);
            const float* Bs = (const float*)(sm + G_BOFF + (size_t)s * GSTAGE_B);
#pragma unroll
            for (int kbp = 0; kbp < 2; kbp++) {        // 16 k per pass
                uint32_t ae[4][4], ao[4][4], be[4][2], bo[4][2];
#pragma unroll
                for (int mt = 0; mt < 4; mt++) {
                    const float4 lo = *(const float4*)(As + (wm + mt * 16 + g) * GS + kbp * 16 + tq * 4);
                    const float4 hi = *(const float4*)(As + (wm + mt * 16 + g + 8) * GS + kbp * 16 + tq * 4);
                    ae[mt][0] = __float_as_uint(lo.x); ae[mt][1] = __float_as_uint(hi.x);
                    ae[mt][2] = __float_as_uint(lo.y); ae[mt][3] = __float_as_uint(hi.y);
                    ao[mt][0] = __float_as_uint(lo.z); ao[mt][1] = __float_as_uint(hi.z);
                    ao[mt][2] = __float_as_uint(lo.w); ao[mt][3] = __float_as_uint(hi.w);
                }
#pragma unroll
                for (int nt = 0; nt < 4; nt++) {
                    const float4 bb = *(const float4*)(Bs + (wn + nt * 8 + g) * GS + kbp * 16 + tq * 4);
                    be[nt][0] = __float_as_uint(bb.x); be[nt][1] = __float_as_uint(bb.y);
                    bo[nt][0] = __float_as_uint(bb.z); bo[nt][1] = __float_as_uint(bb.w);
                }
#pragma unroll
                for (int mt = 0; mt < 4; mt++)
#pragma unroll
                    for (int nt = 0; nt < 4; nt++)
                        mma8(c[mt][nt], ae[mt], be[nt]);
#pragma unroll
                for (int mt = 0; mt < 4; mt++)
#pragma unroll
                    for (int nt = 0; nt < 4; nt++)
                        mma8(c[mt][nt], ao[mt], bo[nt]);
            }
        }
        __syncthreads();
        if (t + 2 < KT)
            gemm_prefetch(sb, s, A, Bt, K, bm, bn, (t + 2) * 32, tid);
        CP_COMMIT();
    }

    // Epilogue: c0:(g,2tq) c1:(g,2tq+1) c2:(g+8,2tq) c3:(g+8,2tq+1)
#pragma unroll
    for (int mt = 0; mt < 4; mt++) {
#pragma unroll
        for (int nt = 0; nt < 4; nt++) {
            const int col = bn + wn + nt * 8 + 2 * tq;
            const float b0 = bias[col], b1 = bias[col + 1];
            const int r0 = bm + wm + mt * 16 + g;
            const int r1 = r0 + 8;
            float v00 = c[mt][nt][0] + b0, v01 = c[mt][nt][1] + b1;
            float v10 = c[mt][nt][2] + b0, v11 = c[mt][nt][3] + b1;
            if (qkv_mode) {
                v00 = f2tff(v00); v01 = f2tff(v01);
                v10 = f2tff(v10); v11 = f2tff(v11);
                const int which = col >> 10;
                const int h  = (col >> 6) & 15;
                const int dd = col & 63;
                const int bh0 = (r0 >> 11) * H_ + h, l0 = r0 & 2047;
                const int bh1 = (r1 >> 11) * H_ + h, l1 = r1 & 2047;
                if (which == 2) {
                    // V: [bh][d][vperm16(l)]
                    const int p0 = vperm16(l0), p1 = vperm16(l1);
                    g_v[((size_t)bh0 * HD_ + dd) * L_ + p0]     = v00;
                    g_v[((size_t)bh0 * HD_ + dd + 1) * L_ + p0] = v01;
                    g_v[((size_t)bh1 * HD_ + dd) * L_ + p1]     = v10;
                    g_v[((size_t)bh1 * HD_ + dd + 1) * L_ + p1] = v11;
                } else {
                    float* tgt = (which == 0) ? g_q : g_k;
                    const int pd0 = perm16(dd), pd1 = perm16(dd + 1);
                    float* d0 = tgt + ((size_t)bh0 * L_ + l0) * HD_;
                    float* d1 = tgt + ((size_t)bh1 * L_ + l1) * HD_;
                    d0[pd0] = v00; d0[pd1] = v01;
                    d1[pd0] = v10; d1[pd1] = v11;
                }
            } else {
                *(float2*)(C + (size_t)r0 * N + col) = make_float2(v00, v01);
                *(float2*)(C + (size_t)r1 * N + col) = make_float2(v10, v11);
            }
        }
    }
}

// ===========================================================================
// Block-causal flash attention on mma.sync tf32.
// K smem [key][64] XOR-swizzled (perm16 d), V smem [d][128] XOR-swizzled
// (vperm16 keys). All fragment loads LDS.128. 96 KB -> 2 CTAs/SM.
// ===========================================================================
#define K_STAGE_B (128 * 64 * 4)             // 32768
#define AT_VOFF   (2 * K_STAGE_B)            // 65536
#define ATTN_SMEM (AT_VOFF + HD_ * 128 * 4)  // 98304

__device__ __forceinline__ void attn_prefetch_k(uint32_t dst, const float* src, int tid)
{
#pragma unroll
    for (int i = 0; i < 8; i++) {
        const int idx = tid + i * 256;          // 0..2047
        const int r = idx >> 4, c = idx & 15;   // 128 rows x 16 granules
        cp16(dst + r * 256 + ((c ^ ((r & 3) << 2)) << 4), src + r * 64 + c * 4);
    }
}
__device__ __forceinline__ void attn_prefetch_v(uint32_t dst, const float* src, int tid)
{
#pragma unroll
    for (int i = 0; i < 8; i++) {
        const int idx = tid + i * 256;          // 0..2047
        const int r = idx >> 5, c = idx & 31;   // 64 d-rows x 32 granules
        cp16(dst + r * 512 + ((c ^ ((r & 7) << 2)) << 4), src + (size_t)r * L_ + c * 4);
    }
}

__global__ __launch_bounds__(256, 2) void attn_mma_kernel(float* __restrict__ ctx)
{
    extern __shared__ __align__(16) char sm[];
    const uint32_t sb = smem_u32(sm);
    const int tid = threadIdx.x, wid = tid >> 5, lane = tid & 31;
    const int g = lane >> 2, tq = lane & 3;
    const int qc = 15 - (int)blockIdx.x;
    const int bh = blockIdx.y, b = bh >> 4, h = bh & 15;
    const size_t head = (size_t)bh * L_ * HD_;
    const int m0 = wid * 16;

    // Q fragments (tf32-rounded, perm16 d in gmem); fold in 1/8
    uint32_t qe[4][4], qo[4][4];
    {
        const float* qb = g_q + head + (size_t)(qc * CHUNK_ + m0) * HD_;
#pragma unroll
        for (int kbp = 0; kbp < 4; kbp++) {
            const float4 lo = *(const float4*)(qb + g * 64 + kbp * 16 + tq * 4);
            const float4 hi = *(const float4*)(qb + (g + 8) * 64 + kbp * 16 + tq * 4);
            qe[kbp][0] = __float_as_uint(lo.x * 0.125f); qe[kbp][1] = __float_as_uint(hi.x * 0.125f);
            qe[kbp][2] = __float_as_uint(lo.y * 0.125f); qe[kbp][3] = __float_as_uint(hi.y * 0.125f);
            qo[kbp][0] = __float_as_uint(lo.z * 0.125f); qo[kbp][1] = __float_as_uint(hi.z * 0.125f);
            qo[kbp][2] = __float_as_uint(lo.w * 0.125f); qo[kbp][3] = __float_as_uint(hi.w * 0.125f);
        }
    }

    float o[8][4];
#pragma unroll
    for (int nv = 0; nv < 8; nv++)
#pragma unroll
        for (int i = 0; i < 4; i++) o[nv][i] = 0.f;
    float m_lo = -1e30f, m_hi = -1e30f, ls_lo = 0.f, ls_hi = 0.f;

    // prologue: K(0) -> Kbuf0, V(0) -> Vbuf
    attn_prefetch_k(sb, g_k + head, tid);
    attn_prefetch_v(sb + AT_VOFF, g_v + head, tid);
    CP_COMMIT();

    int s = 0;
    const int kswz = (g & 3) << 2;
    const int vswz = g << 2;
    for (int kc = 0; kc <= qc; kc++) {
        CP_WAIT0();
        __syncthreads();
        const float* Ks = (const float*)(sm + (size_t)s * K_STAGE_B);
        const float* Vs = (const float*)(sm + AT_VOFF);

        // S = Q K^T  (m16 x n128, k64)
        float sc[16][4];
#pragma unroll
        for (int nt = 0; nt < 16; nt++) {
            sc[nt][0] = sc[nt][1] = sc[nt][2] = sc[nt][3] = 0.f;
            const float* kp = Ks + (nt * 8 + g) * 64;
#pragma unroll
            for (int kbp = 0; kbp < 4; kbp++) {
                const float4 bb = *(const float4*)(kp + (((kbp * 4 + tq) ^ kswz) << 2));
                uint32_t be[2], bo[2];
                be[0] = __float_as_uint(bb.x); be[1] = __float_as_uint(bb.y);
                bo[0] = __float_as_uint(bb.z); bo[1] = __float_as_uint(bb.w);
                mma8(sc[nt], qe[kbp], be);
                mma8(sc[nt], qo[kbp], bo);
            }
        }

        // prefetch next K into the other K buffer
        if (kc < qc)
            attn_prefetch_k(sb + (uint32_t)(s ^ 1) * K_STAGE_B,
                            g_k + head + (size_t)(kc + 1) * CHUNK_ * HD_, tid);
        CP_COMMIT();

        // online softmax
        float smx_lo = -1e30f, smx_hi = -1e30f;
#pragma unroll
        for (int nt = 0; nt < 16; nt++) {
            smx_lo = fmaxf(smx_lo, fmaxf(sc[nt][0], sc[nt][1]));
            smx_hi = fmaxf(smx_hi, fmaxf(sc[nt][2], sc[nt][3]));
        }
        smx_lo = fmaxf(smx_lo, __shfl_xor_sync(0xffffffffu, smx_lo, 1));
        smx_lo = fmaxf(smx_lo, __shfl_xor_sync(0xffffffffu, smx_lo, 2));
        smx_hi = fmaxf(smx_hi, __shfl_xor_sync(0xffffffffu, smx_hi, 1));
        smx_hi = fmaxf(smx_hi, __shfl_xor_sync(0xffffffffu, smx_hi, 2));
        const float mn_lo = fmaxf(m_lo, smx_lo), mn_hi = fmaxf(m_hi, smx_hi);
        const float corr_lo = __expf(m_lo - mn_lo), corr_hi = __expf(m_hi - mn_hi);
        m_lo = mn_lo; m_hi = mn_hi;
        ls_lo *= corr_lo; ls_hi *= corr_hi;

        // p = exp(s - m), tf32-rounded in place: sc becomes the PV A-fragment
#pragma unroll
        for (int nt = 0; nt < 16; nt++) {
            const float p0 = __expf(sc[nt][0] - mn_lo), p1 = __expf(sc[nt][1] - mn_lo);
            const float p2 = __expf(sc[nt][2] - mn_hi), p3 = __expf(sc[nt][3] - mn_hi);
            ls_lo += p0 + p1; ls_hi += p2 + p3;
            sc[nt][0] = __uint_as_float(f2tf(p0));
            sc[nt][1] = __uint_as_float(f2tf(p1));
            sc[nt][2] = __uint_as_float(f2tf(p2));
            sc[nt][3] = __uint_as_float(f2tf(p3));
        }

#pragma unroll
        for (int nv = 0; nv < 8; nv++) {
            o[nv][0] *= corr_lo; o[nv][1] *= corr_lo;
            o[nv][2] *= corr_hi; o[nv][3] *= corr_hi;
        }

        // O += P V  (m16 x n64, k128). A-frag = sc directly (relabel trick);
        // V float4 supplies keys for two adjacent 8-groups.
#pragma unroll
        for (int kbp = 0; kbp < 8; kbp++) {
            uint32_t pe[4], po[4];
            pe[0] = __float_as_uint(sc[2 * kbp][0]);
            pe[1] = __float_as_uint(sc[2 * kbp][2]);
            pe[2] = __float_as_uint(sc[2 * kbp][1]);
            pe[3] = __float_as_uint(sc[2 * kbp][3]);
            po[0] = __float_as_uint(sc[2 * kbp + 1][0]);
            po[1] = __float_as_uint(sc[2 * kbp + 1][2]);
            po[2] = __float_as_uint(sc[2 * kbp + 1][1]);
            po[3] = __float_as_uint(sc[2 * kbp + 1][3]);
#pragma unroll
            for (int nv = 0; nv < 8; nv++) {
                const float4 vv = *(const float4*)(Vs + (nv * 8 + g) * 128 +
                                                   (((kbp * 4 + tq) ^ vswz) << 2));
                uint32_t ve[2], vo[2];
                ve[0] = __float_as_uint(vv.x); ve[1] = __float_as_uint(vv.y);
                vo[0] = __float_as_uint(vv.z); vo[1] = __float_as_uint(vv.w);
                mma8(o[nv], pe, ve);
                mma8(o[nv], po, vo);
            }
        }

        __syncthreads();   // all warps done reading V before overwrite
        if (kc < qc)
            attn_prefetch_v(sb + AT_VOFF,
                            g_v + head + (size_t)(kc + 1) * CHUNK_, tid);
        CP_COMMIT();
        s ^= 1;
    }

    ls_lo += __shfl_xor_sync(0xffffffffu, ls_lo, 1);
    ls_lo += __shfl_xor_sync(0xffffffffu, ls_lo, 2);
    ls_hi += __shfl_xor_sync(0xffffffffu, ls_hi, 1);
    ls_hi += __shfl_xor_sync(0xffffffffu, ls_hi, 2);
    const float il = 1.f / ls_lo, ih = 1.f / ls_hi;

    // write ctx tf32-rounded, perm16 cols for the out-proj GEMM
    const int r0 = qc * CHUNK_ + m0 + g;
#pragma unroll
    for (int nv = 0; nv < 8; nv++) {
        const int col = h * HD_ + nv * 8 + 2 * tq;
        const int p0 = perm16(col), p1 = perm16(col + 1);
        float* c0 = ctx + ((size_t)b * L_ + r0) * D_;
        float* c1 = ctx + ((size_t)b * L_ + r0 + 8) * D_;
        c0[p0] = f2tff(o[nv][0] * il); c0[p1] = f2tff(o[nv][1] * il);
        c1[p0] = f2tff(o[nv][2] * ih); c1[p1] = f2tff(o[nv][3] * ih);
    }
}

// ---------------------------------------------------------------------------
extern "C" void kernel_launch(void* const* d_in, const int* in_sizes, int n_in,
                              void* d_out, int out_size)
{
    const float* x    = (const float*)d_in[0];
    const float* Wqkv = (const float*)d_in[1];
    const float* bqkv = (const float*)d_in[2];
    const float* Wout = (const float*)d_in[3];
    const float* bout = (const float*)d_in[4];
    float* out = (float*)d_out;

    (void)in_sizes; (void)n_in; (void)out_size;

    cudaFuncSetAttribute(gemm_mma_kernel, cudaFuncAttributeMaxDynamicSharedMemorySize, GEMM_SMEM);
    cudaFuncSetAttribute(attn_mma_kernel, cudaFuncAttributeMaxDynamicSharedMemorySize, ATTN_SMEM);

    float *ctx_ptr, *xr, *wqkvr, *woutr;
    cudaGetSymbolAddress((void**)&ctx_ptr, g_ctx);
    cudaGetSymbolAddress((void**)&xr, g_xr);
    cudaGetSymbolAddress((void**)&wqkvr, g_wqkvr);
    cudaGetSymbolAddress((void**)&woutr, g_woutr);

    // 0. prep: round+perm16 x; transpose+round+perm16 weights
    {
        const int n16 = M_ROWS * D_ / 16;
        roundperm_kernel<<<(n16 + 255) / 256, 256>>>((const float4*)x, (float4*)xr, n16);
        dim3 blk(32, 8);
        transperm_kernel<<<dim3(QKV_N / 32, D_ / 32), blk>>>(Wqkv, wqkvr, D_, QKV_N);
        transperm_kernel<<<dim3(D_ / 32, D_ / 32), blk>>>(Wout, woutr, D_, D_);
    }
    // 1. QKV projection + scatter: q/k [bh][l][perm16(d)], v [bh][d][vperm16(l)]
    {
        dim3 grid(QKV_N / 128, M_ROWS / 128);   // (24, 32)
        gemm_mma_kernel<<<grid, 256, GEMM_SMEM>>>(xr, wqkvr, bqkv, nullptr,
                                                  M_ROWS, QKV_N, D_, 1);
    }
    // 2. Block-causal attention -> g_ctx (perm16, tf32-rounded)
    {
        dim3 grid(L_ / CHUNK_, B_ * H_);        // (16, 32)
        attn_mma_kernel<<<grid, 256, ATTN_SMEM>>>(ctx_ptr);
    }
    // 3. Output projection -> d_out
    {
        dim3 grid(D_ / 128, M_ROWS / 128);      // (8, 32)
        gemm_mma_kernel<<<grid, 256, GEMM_SMEM>>>(ctx_ptr, woutr, bout, out,
                                                  M_ROWS, D_, D_, 0);
    }
}

// round 8
// speedup vs baseline: 1.1240x; 1.1240x over previous
#include <cuda_runtime.h>
#include <cstdint>

// Problem constants
#define B_      2
#define L_      2048
#define D_      1024
#define H_      16
#define HD_     64
#define CHUNK_  128
#define M_ROWS  (B_ * L_)          // 4096
#define QKV_N   (3 * D_)           // 3072

// Scratch (device globals — no allocation allowed)
__device__ __align__(16) float g_q[(size_t)B_ * H_ * L_ * HD_];     // [bh][l][perm(d)]
__device__ __align__(16) float g_k[(size_t)B_ * H_ * L_ * HD_];     // [bh][l][perm(d)]
__device__ __align__(16) float g_v[(size_t)B_ * H_ * HD_ * L_];     // [bh][d][l]  (UNpermuted keys)
__device__ __align__(16) float g_ctx[(size_t)B_ * L_ * D_];         // [m][perm(c)]
__device__ __align__(16) float g_xr[(size_t)M_ROWS * D_];           // [m][perm(k)]
__device__ __align__(16) float g_wqkvr[(size_t)QKV_N * D_];         // [n][perm(k)] (transposed)
__device__ __align__(16) float g_woutr[(size_t)D_ * D_];            // [n][perm(k)] (transposed)

// ===========================================================================
// Helpers
// ===========================================================================
__device__ __forceinline__ uint32_t smem_u32(const void* p) {
    uint32_t a;
    asm("{ .reg .u64 t; cvta.to.shared.u64 t, %1; cvt.u32.u64 %0, t; }" : "=r"(a) : "l"(p));
    return a;
}
__device__ __forceinline__ uint32_t f2tf(float x) {
    uint32_t r;
    asm("cvt.rna.tf32.f32 %0, %1;" : "=r"(r) : "f"(x));
    return r;
}
__device__ __forceinline__ float f2tff(float x) { return __uint_as_float(f2tf(x)); }
__device__ __forceinline__ float ex2(float x) {
    float r;
    asm("ex2.approx.ftz.f32 %0, %1;" : "=f"(r) : "f"(x));
    return r;
}

// K-dim permutation: within each 8-group, b -> ((b&3)<<1)|(b>>2)
// so that fragment pairs (k, k+4) land adjacent -> 64-bit loads.
__device__ __forceinline__ int perm_idx(int i) {
    return (i & ~7) | ((i & 3) << 1) | ((i >> 2) & 1);
}

// m16n8k8 tf32 mma: D = A*B + D  (A row-major, B col-major)
__device__ __forceinline__ void mma8(float* c, const uint32_t* a, const uint32_t* b) {
    asm volatile(
        "mma.sync.aligned.m16n8k8.row.col.f32.tf32.tf32.f32 "
        "{%0,%1,%2,%3}, {%4,%5,%6,%7}, {%8,%9}, {%0,%1,%2,%3};"
        : "+f"(c[0]), "+f"(c[1]), "+f"(c[2]), "+f"(c[3])
        : "r"(a[0]), "r"(a[1]), "r"(a[2]), "r"(a[3]), "r"(b[0]), "r"(b[1]));
}

__device__ __forceinline__ void cp16(uint32_t dst, const void* src) {
    asm volatile("cp.async.cg.shared.global [%0], [%1], 16;" :: "r"(dst), "l"(src));
}
#define CP_COMMIT() asm volatile("cp.async.commit_group;" ::: "memory")
#define CP_WAIT0()  asm volatile("cp.async.wait_group 0;" ::: "memory")
#define CP_WAIT1()  asm volatile("cp.async.wait_group 1;" ::: "memory")

// ===========================================================================
// Prep kernels
// ===========================================================================
__global__ __launch_bounds__(256) void roundperm_kernel(
    const float4* __restrict__ in, float4* __restrict__ out, int n8)
{
    const int i = blockIdx.x * blockDim.x + threadIdx.x;
    if (i < n8) {
        const float4 a = in[2 * i], b = in[2 * i + 1];
        out[2 * i]     = make_float4(f2tff(a.x), f2tff(b.x), f2tff(a.y), f2tff(b.y));
        out[2 * i + 1] = make_float4(f2tff(a.z), f2tff(b.z), f2tff(a.w), f2tff(b.w));
    }
}

// W[K][N] -> Wt[N][perm(K)] with tf32 rounding (tiled transpose)
__global__ __launch_bounds__(256) void transperm_kernel(
    const float* __restrict__ in, float* __restrict__ out, int K, int N)
{
    __shared__ float tile[32][33];
    const int k0 = blockIdx.y * 32, n0 = blockIdx.x * 32;
    const int tx = threadIdx.x, ty = threadIdx.y;    // 32 x 8
#pragma unroll
    for (int i = 0; i < 4; i++)
        tile[ty + 8 * i][tx] = in[(size_t)(k0 + ty + 8 * i) * N + n0 + tx];
    __syncthreads();
    const int kp = k0 + perm_idx(tx);
#pragma unroll
    for (int i = 0; i < 4; i++)
        out[(size_t)(n0 + ty + 8 * i) * K + kp] = f2tff(tile[tx][ty + 8 * i]);
}

// ===========================================================================
// tf32 mma GEMM (identical to the proven R6 kernel)
// ===========================================================================
#define GS 40
#define GSTAGE_B (128 * GS * 4)
#define G_BOFF   (2 * GSTAGE_B)
#define GEMM_SMEM (4 * GSTAGE_B)   // 81920 bytes

__device__ __forceinline__ void gemm_prefetch(
    uint32_t sb, int s, const float* A, const float* Bt,
    int K, int bm, int bn, int k0, int tid)
{
    const uint32_t a_st = sb + (uint32_t)s * GSTAGE_B;
    const uint32_t b_st = sb + G_BOFF + (uint32_t)s * GSTAGE_B;
#pragma unroll
    for (int i = 0; i < 4; i++) {
        const int idx = tid + i * 256;
        const int r = idx >> 3, c = idx & 7;
        cp16(a_st + r * (GS * 4) + c * 16, A + (size_t)(bm + r) * K + k0 + c * 4);
    }
#pragma unroll
    for (int i = 0; i < 4; i++) {
        const int idx = tid + i * 256;
        const int r = idx >> 3, c = idx & 7;
        cp16(b_st + r * (GS * 4) + c * 16, Bt + (size_t)(bn + r) * K + k0 + c * 4);
    }
}

__global__ __launch_bounds__(256, 2) void gemm_mma_kernel(
    const float* __restrict__ A, const float* __restrict__ Bt,
    const float* __restrict__ bias, float* __restrict__ C,
    int M, int N, int K, int qkv_mode)
{
    extern __shared__ __align__(16) char sm[];
    const uint32_t sb = smem_u32(sm);
    const int tid = threadIdx.x, wid = tid >> 5, lane = tid & 31;
    const int g = lane >> 2, tq = lane & 3;
    const int bm = blockIdx.y * 128, bn = blockIdx.x * 128;
    const int wm = (wid >> 2) * 64, wn = (wid & 3) * 32;

    float c[4][4][4];
#pragma unroll
    for (int mt = 0; mt < 4; mt++)
#pragma unroll
        for (int nt = 0; nt < 4; nt++)
#pragma unroll
            for (int i = 0; i < 4; i++) c[mt][nt][i] = 0.f;

    const int KT = K >> 5;
    gemm_prefetch(sb, 0, A, Bt, K, bm, bn, 0, tid);  CP_COMMIT();
    gemm_prefetch(sb, 1, A, Bt, K, bm, bn, 32, tid); CP_COMMIT();

    for (int t = 0; t < KT; t++) {
        CP_WAIT1();
        __syncthreads();
        const int s = t & 1;
        {
            const float* As = (const float*)(sm + (size_t)s * GSTAGE_B);
            const float* Bs = (const float*)(sm + G_BOFF + (size_t)s * GSTAGE_B);
#pragma unroll
            for (int kb = 0; kb < 4; kb++) {
                uint32_t af[4][4], bf[4][2];
#pragma unroll
                for (int mt = 0; mt < 4; mt++) {
                    const float2 lo = *(const float2*)(As + (wm + mt * 16 + g) * GS + kb * 8 + tq * 2);
                    const float2 hi = *(const float2*)(As + (wm + mt * 16 + g + 8) * GS + kb * 8 + tq * 2);
                    af[mt][0] = __float_as_uint(lo.x);
                    af[mt][1] = __float_as_uint(hi.x);
                    af[mt][2] = __float_as_uint(lo.y);
                    af[mt][3] = __float_as_uint(hi.y);
                }
#pragma unroll
                for (int nt = 0; nt < 4; nt++) {
                    const float2 bb = *(const float2*)(Bs + (wn + nt * 8 + g) * GS + kb * 8 + tq * 2);
                    bf[nt][0] = __float_as_uint(bb.x);
                    bf[nt][1] = __float_as_uint(bb.y);
                }
#pragma unroll
                for (int mt = 0; mt < 4; mt++)
#pragma unroll
                    for (int nt = 0; nt < 4; nt++)
                        mma8(c[mt][nt], af[mt], bf[nt]);
            }
        }
        __syncthreads();
        if (t + 2 < KT)
            gemm_prefetch(sb, s, A, Bt, K, bm, bn, (t + 2) * 32, tid);
        CP_COMMIT();
    }

    // Epilogue: c0:(g,2tq) c1:(g,2tq+1) c2:(g+8,2tq) c3:(g+8,2tq+1)
#pragma unroll
    for (int mt = 0; mt < 4; mt++) {
#pragma unroll
        for (int nt = 0; nt < 4; nt++) {
            const int col = bn + wn + nt * 8 + 2 * tq;
            const float b0 = bias[col], b1 = bias[col + 1];
            const int r0 = bm + wm + mt * 16 + g;
            const int r1 = r0 + 8;
            float v00 = c[mt][nt][0] + b0, v01 = c[mt][nt][1] + b1;
            float v10 = c[mt][nt][2] + b0, v11 = c[mt][nt][3] + b1;
            if (qkv_mode) {
                v00 = f2tff(v00); v01 = f2tff(v01);
                v10 = f2tff(v10); v11 = f2tff(v11);
                const int which = col >> 10;
                const int h  = (col >> 6) & 15;
                const int dd = col & 63;
                const int bh0 = (r0 >> 11) * H_ + h, l0 = r0 & 2047;
                const int bh1 = (r1 >> 11) * H_ + h, l1 = r1 & 2047;
                if (which == 2) {
                    // V: [bh][d][l]  (keys UNpermuted — C-frag relabeling trick)
                    g_v[((size_t)bh0 * HD_ + dd) * L_ + l0]     = v00;
                    g_v[((size_t)bh0 * HD_ + dd + 1) * L_ + l0] = v01;
                    g_v[((size_t)bh1 * HD_ + dd) * L_ + l1]     = v10;
                    g_v[((size_t)bh1 * HD_ + dd + 1) * L_ + l1] = v11;
                } else {
                    float* tgt = (which == 0) ? g_q : g_k;
                    const int pd0 = perm_idx(dd), pd1 = perm_idx(dd + 1);
                    float* d0 = tgt + ((size_t)bh0 * L_ + l0) * HD_;
                    float* d1 = tgt + ((size_t)bh1 * L_ + l1) * HD_;
                    d0[pd0] = v00; d0[pd1] = v01;
                    d1[pd0] = v10; d1[pd1] = v11;
                }
            } else {
                *(float2*)(C + (size_t)r0 * N + col) = make_float2(v00, v01);
                *(float2*)(C + (size_t)r1 * N + col) = make_float2(v10, v11);
            }
        }
    }
}

// ===========================================================================
// Block-causal flash attention on mma.sync tf32.
// R6 structure + (a) split-wait cp.async groups so V latency hides behind
// S-mma/softmax, (b) exp2 with log2e folded into Q (base-2 softmax domain).
// ===========================================================================
#define KS_ 72
#define VS_ 136
#define K_STAGE_B (128 * KS_ * 4)            // 36864
#define AT_VOFF   (2 * K_STAGE_B)            // 73728
#define ATTN_SMEM (AT_VOFF + HD_ * VS_ * 4)  // 108544

__device__ __forceinline__ void attn_prefetch_k(uint32_t dst, const float* src, int tid)
{
#pragma unroll
    for (int i = 0; i < 8; i++) {
        const int idx = tid + i * 256;
        const int r = idx >> 4, c = idx & 15;
        cp16(dst + r * (KS_ * 4) + c * 16, src + r * 64 + c * 4);
    }
}
__device__ __forceinline__ void attn_prefetch_v(uint32_t dst, const float* src, int tid)
{
#pragma unroll
    for (int i = 0; i < 8; i++) {
        const int idx = tid + i * 256;
        const int r = idx >> 5, c = idx & 31; // 64 d-rows x 32 16B-chunks
        cp16(dst + r * (VS_ * 4) + c * 16, src + (size_t)r * L_ + c * 4);
    }
}

__global__ __launch_bounds__(256, 2) void attn_mma_kernel(float* __restrict__ ctx)
{
    extern __shared__ __align__(16) char sm[];
    const uint32_t sb = smem_u32(sm);
    const int tid = threadIdx.x, wid = tid >> 5, lane = tid & 31;
    const int g = lane >> 2, tq = lane & 3;
    const int qc = 15 - (int)blockIdx.x;
    const int bh = blockIdx.y, b = bh >> 4, h = bh & 15;
    const size_t head = (size_t)bh * L_ * HD_;
    const int m0 = wid * 16;

    // Q fragments; fold 1/8 * log2(e) so softmax runs in base-2 domain
    const float QSCALE = 0.125f * 1.4426950408889634f;
    uint32_t qa[8][4];
    {
        const float* qb = g_q + head + (size_t)(qc * CHUNK_ + m0) * HD_;
#pragma unroll
        for (int kb = 0; kb < 8; kb++) {
            const float2 lo = *(const float2*)(qb + g * 64 + kb * 8 + tq * 2);
            const float2 hi = *(const float2*)(qb + (g + 8) * 64 + kb * 8 + tq * 2);
            qa[kb][0] = __float_as_uint(lo.x * QSCALE);
            qa[kb][1] = __float_as_uint(hi.x * QSCALE);
            qa[kb][2] = __float_as_uint(lo.y * QSCALE);
            qa[kb][3] = __float_as_uint(hi.y * QSCALE);
        }
    }

    float o[8][4];
#pragma unroll
    for (int nv = 0; nv < 8; nv++)
#pragma unroll
        for (int i = 0; i < 4; i++) o[nv][i] = 0.f;
    float m_lo = -1e30f, m_hi = -1e30f, ls_lo = 0.f, ls_hi = 0.f;

    // prologue: K(0) and V(0) in SEPARATE commit groups (K older)
    attn_prefetch_k(sb, g_k + head, tid);
    CP_COMMIT();
    attn_prefetch_v(sb + AT_VOFF, g_v + head, tid);
    CP_COMMIT();

    int s = 0;
    for (int kc = 0; kc <= qc; kc++) {
        // wait K(kc) only (V(kc) may still be in flight)
        CP_WAIT1();
        __syncthreads();
        const float* Ks = (const float*)(sm + (size_t)s * K_STAGE_B);
        const float* Vs = (const float*)(sm + AT_VOFF);

        // S = Q K^T  (m16 x n128, k64), scores in log2 domain
        float sc[16][4];
#pragma unroll
        for (int nt = 0; nt < 16; nt++) {
            sc[nt][0] = sc[nt][1] = sc[nt][2] = sc[nt][3] = 0.f;
            const float* kp = Ks + (nt * 8 + g) * KS_;
#pragma unroll
            for (int kb = 0; kb < 8; kb++) {
                const float2 bb = *(const float2*)(kp + kb * 8 + tq * 2);
                uint32_t bfr[2];
                bfr[0] = __float_as_uint(bb.x);
                bfr[1] = __float_as_uint(bb.y);
                mma8(sc[nt], qa[kb], bfr);
            }
        }

        // prefetch next K into the other K buffer (own commit group)
        if (kc < qc)
            attn_prefetch_k(sb + (uint32_t)(s ^ 1) * K_STAGE_B,
                            g_k + head + (size_t)(kc + 1) * CHUNK_ * HD_, tid);
        CP_COMMIT();

        // online softmax (base-2)
        float smx_lo = -1e30f, smx_hi = -1e30f;
#pragma unroll
        for (int nt = 0; nt < 16; nt++) {
            smx_lo = fmaxf(smx_lo, fmaxf(sc[nt][0], sc[nt][1]));
            smx_hi = fmaxf(smx_hi, fmaxf(sc[nt][2], sc[nt][3]));
        }
        smx_lo = fmaxf(smx_lo, __shfl_xor_sync(0xffffffffu, smx_lo, 1));
        smx_lo = fmaxf(smx_lo, __shfl_xor_sync(0xffffffffu, smx_lo, 2));
        smx_hi = fmaxf(smx_hi, __shfl_xor_sync(0xffffffffu, smx_hi, 1));
        smx_hi = fmaxf(smx_hi, __shfl_xor_sync(0xffffffffu, smx_hi, 2));
        const float mn_lo = fmaxf(m_lo, smx_lo), mn_hi = fmaxf(m_hi, smx_hi);
        const float corr_lo = ex2(m_lo - mn_lo), corr_hi = ex2(m_hi - mn_hi);
        m_lo = mn_lo; m_hi = mn_hi;
        ls_lo *= corr_lo; ls_hi *= corr_hi;

        // p = 2^(s - m), tf32-rounded in place: sc becomes the PV A-fragment
#pragma unroll
        for (int nt = 0; nt < 16; nt++) {
            const float p0 = ex2(sc[nt][0] - mn_lo), p1 = ex2(sc[nt][1] - mn_lo);
            const float p2 = ex2(sc[nt][2] - mn_hi), p3 = ex2(sc[nt][3] - mn_hi);
            ls_lo += p0 + p1; ls_hi += p2 + p3;
            sc[nt][0] = __uint_as_float(f2tf(p0));
            sc[nt][1] = __uint_as_float(f2tf(p1));
            sc[nt][2] = __uint_as_float(f2tf(p2));
            sc[nt][3] = __uint_as_float(f2tf(p3));
        }

#pragma unroll
        for (int nv = 0; nv < 8; nv++) {
            o[nv][0] *= corr_lo; o[nv][1] *= corr_lo;
            o[nv][2] *= corr_hi; o[nv][3] *= corr_hi;
        }

        // now wait V(kc) (older of the two outstanding groups)
        CP_WAIT1();
        __syncthreads();

        // O += P V  (m16 x n64, k128). A-frag = sc directly (relabel trick).
#pragma unroll
        for (int kb = 0; kb < 16; kb++) {
            uint32_t pa[4];
            pa[0] = __float_as_uint(sc[kb][0]);   // row g,   k-slot tq   (key 2tq)
            pa[1] = __float_as_uint(sc[kb][2]);   // row g+8, k-slot tq
            pa[2] = __float_as_uint(sc[kb][1]);   // row g,   k-slot tq+4 (key 2tq+1)
            pa[3] = __float_as_uint(sc[kb][3]);   // row g+8, k-slot tq+4
#pragma unroll
            for (int nv = 0; nv < 8; nv++) {
                const float2 vv = *(const float2*)(Vs + (nv * 8 + g) * VS_ + kb * 8 + tq * 2);
                uint32_t vb[2];
                vb[0] = __float_as_uint(vv.x);
                vb[1] = __float_as_uint(vv.y);
                mma8(o[nv], pa, vb);
            }
        }

        __syncthreads();   // all warps done reading V before overwrite
        if (kc < qc)
            attn_prefetch_v(sb + AT_VOFF,
                            g_v + head + (size_t)(kc + 1) * CHUNK_, tid);
        CP_COMMIT();
        s ^= 1;
    }

    ls_lo += __shfl_xor_sync(0xffffffffu, ls_lo, 1);
    ls_lo += __shfl_xor_sync(0xffffffffu, ls_lo, 2);
    ls_hi += __shfl_xor_sync(0xffffffffu, ls_hi, 1);
    ls_hi += __shfl_xor_sync(0xffffffffu, ls_hi, 2);
    const float il = 1.f / ls_lo, ih = 1.f / ls_hi;

    // write ctx tf32-rounded, K-permuted for the out-proj GEMM
    const int r0 = qc * CHUNK_ + m0 + g;
#pragma unroll
    for (int nv = 0; nv < 8; nv++) {
        const int col = h * HD_ + nv * 8 + 2 * tq;
        const int p0 = perm_idx(col), p1 = perm_idx(col + 1);
        float* c0 = ctx + ((size_t)b * L_ + r0) * D_;
        float* c1 = ctx + ((size_t)b * L_ + r0 + 8) * D_;
        c0[p0] = f2tff(o[nv][0] * il); c0[p1] = f2tff(o[nv][1] * il);
        c1[p0] = f2tff(o[nv][2] * ih); c1[p1] = f2tff(o[nv][3] * ih);
    }
}

// ---------------------------------------------------------------------------
extern "C" void kernel_launch(void* const* d_in, const int* in_sizes, int n_in,
                              void* d_out, int out_size)
{
    const float* x    = (const float*)d_in[0];
    const float* Wqkv = (const float*)d_in[1];
    const float* bqkv = (const float*)d_in[2];
    const float* Wout = (const float*)d_in[3];
    const float* bout = (const float*)d_in[4];
    float* out = (float*)d_out;

    (void)in_sizes; (void)n_in; (void)out_size;

    cudaFuncSetAttribute(gemm_mma_kernel, cudaFuncAttributeMaxDynamicSharedMemorySize, GEMM_SMEM);
    cudaFuncSetAttribute(attn_mma_kernel, cudaFuncAttributeMaxDynamicSharedMemorySize, ATTN_SMEM);

    float *ctx_ptr, *xr, *wqkvr, *woutr;
    cudaGetSymbolAddress((void**)&ctx_ptr, g_ctx);
    cudaGetSymbolAddress((void**)&xr, g_xr);
    cudaGetSymbolAddress((void**)&wqkvr, g_wqkvr);
    cudaGetSymbolAddress((void**)&woutr, g_woutr);

    // 0. prep: round+permute x; transpose+round+permute weights
    {
        const int n8 = M_ROWS * D_ / 8;
        roundperm_kernel<<<(n8 + 255) / 256, 256>>>((const float4*)x, (float4*)xr, n8);
        dim3 blk(32, 8);
        transperm_kernel<<<dim3(QKV_N / 32, D_ / 32), blk>>>(Wqkv, wqkvr, D_, QKV_N);
        transperm_kernel<<<dim3(D_ / 32, D_ / 32), blk>>>(Wout, woutr, D_, D_);
    }
    // 1. QKV projection + scatter: q/k [bh][l][perm(d)], v [bh][d][l]
    {
        dim3 grid(QKV_N / 128, M_ROWS / 128);   // (24, 32)
        gemm_mma_kernel<<<grid, 256, GEMM_SMEM>>>(xr, wqkvr, bqkv, nullptr,
                                                  M_ROWS, QKV_N, D_, 1);
    }
    // 2. Block-causal attention -> g_ctx (permuted, tf32-rounded)
    {
        dim3 grid(L_ / CHUNK_, B_ * H_);        // (16, 32)
        attn_mma_kernel<<<grid, 256, ATTN_SMEM>>>(ctx_ptr);
    }
    // 3. Output projection -> d_out
    {
        dim3 grid(D_ / 128, M_ROWS / 128);      // (8, 32)
        gemm_mma_kernel<<<grid, 256, GEMM_SMEM>>>(ctx_ptr, woutr, bout, out,
                                                  M_ROWS, D_, D_, 0);
    }
}

// round 9
// speedup vs baseline: 1.2897x; 1.1474x over previous
#include <cuda_runtime.h>
#include <cstdint>

// Problem constants
#define B_      2
#define L_      2048
#define D_      1024
#define H_      16
#define HD_     64
#define CHUNK_  128
#define M_ROWS  (B_ * L_)          // 4096
#define QKV_N   (3 * D_)           // 3072

// Scratch (device globals — no allocation allowed)
__device__ __align__(16) float g_q[(size_t)B_ * H_ * L_ * HD_];     // [bh][l][perm(d)]
__device__ __align__(16) float g_k[(size_t)B_ * H_ * L_ * HD_];     // [bh][l][perm(d)]
__device__ __align__(16) float g_v[(size_t)B_ * H_ * HD_ * L_];     // [bh][d][l]  (UNpermuted keys)
__device__ __align__(16) float g_ctx[(size_t)B_ * L_ * D_];         // [m][perm(c)]
__device__ __align__(16) float g_xr[(size_t)M_ROWS * D_];           // [m][perm(k)]
__device__ __align__(16) float g_wqkvr[(size_t)QKV_N * D_];         // [n][perm(k)] (transposed)
__device__ __align__(16) float g_woutr[(size_t)D_ * D_];            // [n][perm(k)] (transposed)

// ===========================================================================
// Helpers
// ===========================================================================
__device__ __forceinline__ uint32_t smem_u32(const void* p) {
    uint32_t a;
    asm("{ .reg .u64 t; cvta.to.shared.u64 t, %1; cvt.u32.u64 %0, t; }" : "=r"(a) : "l"(p));
    return a;
}
__device__ __forceinline__ uint32_t f2tf(float x) {
    uint32_t r;
    asm("cvt.rna.tf32.f32 %0, %1;" : "=r"(r) : "f"(x));
    return r;
}
__device__ __forceinline__ float f2tff(float x) { return __uint_as_float(f2tf(x)); }
__device__ __forceinline__ float ex2(float x) {
    float r;
    asm("ex2.approx.ftz.f32 %0, %1;" : "=f"(r) : "f"(x));
    return r;
}

// K-dim permutation: within each 8-group, b -> ((b&3)<<1)|(b>>2)
__device__ __forceinline__ int perm_idx(int i) {
    return (i & ~7) | ((i & 3) << 1) | ((i >> 2) & 1);
}

// m16n8k8 tf32 mma: D = A*B + D  (A row-major, B col-major)
__device__ __forceinline__ void mma8(float* c, const uint32_t* a, const uint32_t* b) {
    asm volatile(
        "mma.sync.aligned.m16n8k8.row.col.f32.tf32.tf32.f32 "
        "{%0,%1,%2,%3}, {%4,%5,%6,%7}, {%8,%9}, {%0,%1,%2,%3};"
        : "+f"(c[0]), "+f"(c[1]), "+f"(c[2]), "+f"(c[3])
        : "r"(a[0]), "r"(a[1]), "r"(a[2]), "r"(a[3]), "r"(b[0]), "r"(b[1]));
}

__device__ __forceinline__ void cp16(uint32_t dst, const void* src) {
    asm volatile("cp.async.cg.shared.global [%0], [%1], 16;" :: "r"(dst), "l"(src));
}
#define CP_COMMIT() asm volatile("cp.async.commit_group;" ::: "memory")
#define CP_WAIT0()  asm volatile("cp.async.wait_group 0;" ::: "memory")
#define CP_WAIT1()  asm volatile("cp.async.wait_group 1;" ::: "memory")

// ===========================================================================
// Prep kernels (unchanged)
// ===========================================================================
__global__ __launch_bounds__(256) void roundperm_kernel(
    const float4* __restrict__ in, float4* __restrict__ out, int n8)
{
    const int i = blockIdx.x * blockDim.x + threadIdx.x;
    if (i < n8) {
        const float4 a = in[2 * i], b = in[2 * i + 1];
        out[2 * i]     = make_float4(f2tff(a.x), f2tff(b.x), f2tff(a.y), f2tff(b.y));
        out[2 * i + 1] = make_float4(f2tff(a.z), f2tff(b.z), f2tff(a.w), f2tff(b.w));
    }
}

__global__ __launch_bounds__(256) void transperm_kernel(
    const float* __restrict__ in, float* __restrict__ out, int K, int N)
{
    __shared__ float tile[32][33];
    const int k0 = blockIdx.y * 32, n0 = blockIdx.x * 32;
    const int tx = threadIdx.x, ty = threadIdx.y;    // 32 x 8
#pragma unroll
    for (int i = 0; i < 4; i++)
        tile[ty + 8 * i][tx] = in[(size_t)(k0 + ty + 8 * i) * N + n0 + tx];
    __syncthreads();
    const int kp = k0 + perm_idx(tx);
#pragma unroll
    for (int i = 0; i < 4; i++)
        out[(size_t)(n0 + ty + 8 * i) * K + kp] = f2tff(tile[tx][ty + 8 * i]);
}

// ===========================================================================
// tf32 mma GEMM (identical to the proven R6/R8 kernel)
// ===========================================================================
#define GS 40
#define GSTAGE_B (128 * GS * 4)
#define G_BOFF   (2 * GSTAGE_B)
#define GEMM_SMEM (4 * GSTAGE_B)   // 81920 bytes

__device__ __forceinline__ void gemm_prefetch(
    uint32_t sb, int s, const float* A, const float* Bt,
    int K, int bm, int bn, int k0, int tid)
{
    const uint32_t a_st = sb + (uint32_t)s * GSTAGE_B;
    const uint32_t b_st = sb + G_BOFF + (uint32_t)s * GSTAGE_B;
#pragma unroll
    for (int i = 0; i < 4; i++) {
        const int idx = tid + i * 256;
        const int r = idx >> 3, c = idx & 7;
        cp16(a_st + r * (GS * 4) + c * 16, A + (size_t)(bm + r) * K + k0 + c * 4);
    }
#pragma unroll
    for (int i = 0; i < 4; i++) {
        const int idx = tid + i * 256;
        const int r = idx >> 3, c = idx & 7;
        cp16(b_st + r * (GS * 4) + c * 16, Bt + (size_t)(bn + r) * K + k0 + c * 4);
    }
}

__global__ __launch_bounds__(256, 2) void gemm_mma_kernel(
    const float* __restrict__ A, const float* __restrict__ Bt,
    const float* __restrict__ bias, float* __restrict__ C,
    int M, int N, int K, int qkv_mode)
{
    extern __shared__ __align__(16) char sm[];
    const uint32_t sb = smem_u32(sm);
    const int tid = threadIdx.x, wid = tid >> 5, lane = tid & 31;
    const int g = lane >> 2, tq = lane & 3;
    const int bm = blockIdx.y * 128, bn = blockIdx.x * 128;
    const int wm = (wid >> 2) * 64, wn = (wid & 3) * 32;

    float c[4][4][4];
#pragma unroll
    for (int mt = 0; mt < 4; mt++)
#pragma unroll
        for (int nt = 0; nt < 4; nt++)
#pragma unroll
            for (int i = 0; i < 4; i++) c[mt][nt][i] = 0.f;

    const int KT = K >> 5;
    gemm_prefetch(sb, 0, A, Bt, K, bm, bn, 0, tid);  CP_COMMIT();
    gemm_prefetch(sb, 1, A, Bt, K, bm, bn, 32, tid); CP_COMMIT();

    for (int t = 0; t < KT; t++) {
        CP_WAIT1();
        __syncthreads();
        const int s = t & 1;
        {
            const float* As = (const float*)(sm + (size_t)s * GSTAGE_B);
            const float* Bs = (const float*)(sm + G_BOFF + (size_t)s * GSTAGE_B);
#pragma unroll
            for (int kb = 0; kb < 4; kb++) {
                uint32_t af[4][4], bf[4][2];
#pragma unroll
                for (int mt = 0; mt < 4; mt++) {
                    const float2 lo = *(const float2*)(As + (wm + mt * 16 + g) * GS + kb * 8 + tq * 2);
                    const float2 hi = *(const float2*)(As + (wm + mt * 16 + g + 8) * GS + kb * 8 + tq * 2);
                    af[mt][0] = __float_as_uint(lo.x);
                    af[mt][1] = __float_as_uint(hi.x);
                    af[mt][2] = __float_as_uint(lo.y);
                    af[mt][3] = __float_as_uint(hi.y);
                }
#pragma unroll
                for (int nt = 0; nt < 4; nt++) {
                    const float2 bb = *(const float2*)(Bs + (wn + nt * 8 + g) * GS + kb * 8 + tq * 2);
                    bf[nt][0] = __float_as_uint(bb.x);
                    bf[nt][1] = __float_as_uint(bb.y);
                }
#pragma unroll
                for (int mt = 0; mt < 4; mt++)
#pragma unroll
                    for (int nt = 0; nt < 4; nt++)
                        mma8(c[mt][nt], af[mt], bf[nt]);
            }
        }
        __syncthreads();
        if (t + 2 < KT)
            gemm_prefetch(sb, s, A, Bt, K, bm, bn, (t + 2) * 32, tid);
        CP_COMMIT();
    }

    // Epilogue
#pragma unroll
    for (int mt = 0; mt < 4; mt++) {
#pragma unroll
        for (int nt = 0; nt < 4; nt++) {
            const int col = bn + wn + nt * 8 + 2 * tq;
            const float b0 = bias[col], b1 = bias[col + 1];
            const int r0 = bm + wm + mt * 16 + g;
            const int r1 = r0 + 8;
            float v00 = c[mt][nt][0] + b0, v01 = c[mt][nt][1] + b1;
            float v10 = c[mt][nt][2] + b0, v11 = c[mt][nt][3] + b1;
            if (qkv_mode) {
                v00 = f2tff(v00); v01 = f2tff(v01);
                v10 = f2tff(v10); v11 = f2tff(v11);
                const int which = col >> 10;
                const int h  = (col >> 6) & 15;
                const int dd = col & 63;
                const int bh0 = (r0 >> 11) * H_ + h, l0 = r0 & 2047;
                const int bh1 = (r1 >> 11) * H_ + h, l1 = r1 & 2047;
                if (which == 2) {
                    g_v[((size_t)bh0 * HD_ + dd) * L_ + l0]     = v00;
                    g_v[((size_t)bh0 * HD_ + dd + 1) * L_ + l0] = v01;
                    g_v[((size_t)bh1 * HD_ + dd) * L_ + l1]     = v10;
                    g_v[((size_t)bh1 * HD_ + dd + 1) * L_ + l1] = v11;
                } else {
                    float* tgt = (which == 0) ? g_q : g_k;
                    const int pd0 = perm_idx(dd), pd1 = perm_idx(dd + 1);
                    float* d0 = tgt + ((size_t)bh0 * L_ + l0) * HD_;
                    float* d1 = tgt + ((size_t)bh1 * L_ + l1) * HD_;
                    d0[pd0] = v00; d0[pd1] = v01;
                    d1[pd0] = v10; d1[pd1] = v11;
                }
            } else {
                *(float2*)(C + (size_t)r0 * N + col) = make_float2(v00, v01);
                *(float2*)(C + (size_t)r1 * N + col) = make_float2(v10, v11);
            }
        }
    }
}

// ===========================================================================
// Block-causal flash attention, 512-thread CTA = one q-chunk PAIR (256 rows).
// Warps 0-7 -> chunk 2p, warps 8-15 -> chunk 2p+1 (skip their causal tile).
// K and V both double-buffered -> ONE barrier + ONE wait per tile.
// smem 140 KB -> 1 CTA/SM (RF-full anyway at 512 x 128 regs).
// ===========================================================================
#define KS_ 72
#define VS_ 136
#define K_STAGE_B  (128 * KS_ * 4)           // 36864
#define V_STAGE_B  (HD_ * VS_ * 4)           // 34816
#define AT_VOFF    (2 * K_STAGE_B)           // 73728
#define ATTN_SMEM  (AT_VOFF + 2 * V_STAGE_B) // 143360

__device__ __forceinline__ void attn_prefetch_kv(
    uint32_t kdst, uint32_t vdst, const float* ksrc, const float* vsrc, int tid)
{
#pragma unroll
    for (int i = 0; i < 4; i++) {
        const int idx = tid + i * 512;          // 0..2047
        const int r = idx >> 4, c = idx & 15;   // K: 128 rows x 16 chunks
        cp16(kdst + r * (KS_ * 4) + c * 16, ksrc + r * 64 + c * 4);
    }
#pragma unroll
    for (int i = 0; i < 4; i++) {
        const int idx = tid + i * 512;          // 0..2047
        const int r = idx >> 5, c = idx & 31;   // V: 64 d-rows x 32 chunks
        cp16(vdst + r * (VS_ * 4) + c * 16, vsrc + (size_t)r * L_ + c * 4);
    }
}

__global__ __launch_bounds__(512, 1) void attn_mma_kernel(float* __restrict__ ctx)
{
    extern __shared__ __align__(16) char sm[];
    const uint32_t sb = smem_u32(sm);
    const int tid = threadIdx.x, wid = tid >> 5, lane = tid & 31;
    const int g = lane >> 2, tq = lane & 3;
    // LPT-ish 1D mapping: all heaviest pairs (p=7) first
    const int p  = 7 - ((int)blockIdx.x >> 5);
    const int bh = (int)blockIdx.x & 31;
    const int b = bh >> 4, h = bh & 15;
    const size_t head = (size_t)bh * L_ * HD_;
    const int half = wid >> 3;                  // 0: chunk 2p, 1: chunk 2p+1
    const int my_qc = 2 * p + half;
    const int qc_hi = 2 * p + 1;
    const int m0 = (wid & 7) * 16;

    // Q fragments; fold 1/8 * log2(e) so softmax runs in base-2 domain
    const float QSCALE = 0.125f * 1.4426950408889634f;
    uint32_t qa[8][4];
    {
        const float* qb = g_q + head + (size_t)(my_qc * CHUNK_ + m0) * HD_;
#pragma unroll
        for (int kb = 0; kb < 8; kb++) {
            const float2 lo = *(const float2*)(qb + g * 64 + kb * 8 + tq * 2);
            const float2 hi = *(const float2*)(qb + (g + 8) * 64 + kb * 8 + tq * 2);
            qa[kb][0] = __float_as_uint(lo.x * QSCALE);
            qa[kb][1] = __float_as_uint(hi.x * QSCALE);
            qa[kb][2] = __float_as_uint(lo.y * QSCALE);
            qa[kb][3] = __float_as_uint(hi.y * QSCALE);
        }
    }

    float o[8][4];
#pragma unroll
    for (int nv = 0; nv < 8; nv++)
#pragma unroll
        for (int i = 0; i < 4; i++) o[nv][i] = 0.f;
    float m_lo = -1e30f, m_hi = -1e30f, ls_lo = 0.f, ls_hi = 0.f;

    // prologue: K(0), V(0) -> buffers 0 (single commit group)
    attn_prefetch_kv(sb, sb + AT_VOFF, g_k + head, g_v + head, tid);
    CP_COMMIT();

    int s = 0;
    for (int kc = 0; kc <= qc_hi; kc++) {
        CP_WAIT0();
        __syncthreads();   // KV(kc) visible; everyone done reading old buffers

        // prefetch KV(kc+1) into the other buffers (no conflict with readers)
        if (kc < qc_hi)
            attn_prefetch_kv(sb + (uint32_t)(s ^ 1) * K_STAGE_B,
                             sb + AT_VOFF + (uint32_t)(s ^ 1) * V_STAGE_B,
                             g_k + head + (size_t)(kc + 1) * CHUNK_ * HD_,
                             g_v + head + (size_t)(kc + 1) * CHUNK_, tid);
        CP_COMMIT();

        if (kc <= my_qc) {   // block-causality at warp granularity
            const float* Ks = (const float*)(sm + (size_t)s * K_STAGE_B);
            const float* Vs = (const float*)(sm + AT_VOFF + (size_t)s * V_STAGE_B);

            // S = Q K^T  (m16 x n128, k64), scores in log2 domain
            float sc[16][4];
#pragma unroll
            for (int nt = 0; nt < 16; nt++) {
                sc[nt][0] = sc[nt][1] = sc[nt][2] = sc[nt][3] = 0.f;
                const float* kp = Ks + (nt * 8 + g) * KS_;
#pragma unroll
                for (int kb = 0; kb < 8; kb++) {
                    const float2 bb = *(const float2*)(kp + kb * 8 + tq * 2);
                    uint32_t bfr[2];
                    bfr[0] = __float_as_uint(bb.x);
                    bfr[1] = __float_as_uint(bb.y);
                    mma8(sc[nt], qa[kb], bfr);
                }
            }

            // online softmax (base-2)
            float smx_lo = -1e30f, smx_hi = -1e30f;
#pragma unroll
            for (int nt = 0; nt < 16; nt++) {
                smx_lo = fmaxf(smx_lo, fmaxf(sc[nt][0], sc[nt][1]));
                smx_hi = fmaxf(smx_hi, fmaxf(sc[nt][2], sc[nt][3]));
            }
            smx_lo = fmaxf(smx_lo, __shfl_xor_sync(0xffffffffu, smx_lo, 1));
            smx_lo = fmaxf(smx_lo, __shfl_xor_sync(0xffffffffu, smx_lo, 2));
            smx_hi = fmaxf(smx_hi, __shfl_xor_sync(0xffffffffu, smx_hi, 1));
            smx_hi = fmaxf(smx_hi, __shfl_xor_sync(0xffffffffu, smx_hi, 2));
            const float mn_lo = fmaxf(m_lo, smx_lo), mn_hi = fmaxf(m_hi, smx_hi);
            const float corr_lo = ex2(m_lo - mn_lo), corr_hi = ex2(m_hi - mn_hi);
            m_lo = mn_lo; m_hi = mn_hi;
            ls_lo *= corr_lo; ls_hi *= corr_hi;

            // p = 2^(s - m), tf32-rounded in place: sc becomes PV A-fragment
#pragma unroll
            for (int nt = 0; nt < 16; nt++) {
                const float p0 = ex2(sc[nt][0] - mn_lo), p1 = ex2(sc[nt][1] - mn_lo);
                const float p2 = ex2(sc[nt][2] - mn_hi), p3 = ex2(sc[nt][3] - mn_hi);
                ls_lo += p0 + p1; ls_hi += p2 + p3;
                sc[nt][0] = __uint_as_float(f2tf(p0));
                sc[nt][1] = __uint_as_float(f2tf(p1));
                sc[nt][2] = __uint_as_float(f2tf(p2));
                sc[nt][3] = __uint_as_float(f2tf(p3));
            }

#pragma unroll
            for (int nv = 0; nv < 8; nv++) {
                o[nv][0] *= corr_lo; o[nv][1] *= corr_lo;
                o[nv][2] *= corr_hi; o[nv][3] *= corr_hi;
            }

            // O += P V  (m16 x n64, k128). A-frag = sc directly (relabel trick).
#pragma unroll
            for (int kb = 0; kb < 16; kb++) {
                uint32_t pa[4];
                pa[0] = __float_as_uint(sc[kb][0]);
                pa[1] = __float_as_uint(sc[kb][2]);
                pa[2] = __float_as_uint(sc[kb][1]);
                pa[3] = __float_as_uint(sc[kb][3]);
#pragma unroll
                for (int nv = 0; nv < 8; nv++) {
                    const float2 vv = *(const float2*)(Vs + (nv * 8 + g) * VS_ + kb * 8 + tq * 2);
                    uint32_t vb[2];
                    vb[0] = __float_as_uint(vv.x);
                    vb[1] = __float_as_uint(vv.y);
                    mma8(o[nv], pa, vb);
                }
            }
        }
        s ^= 1;
    }

    ls_lo += __shfl_xor_sync(0xffffffffu, ls_lo, 1);
    ls_lo += __shfl_xor_sync(0xffffffffu, ls_lo, 2);
    ls_hi += __shfl_xor_sync(0xffffffffu, ls_hi, 1);
    ls_hi += __shfl_xor_sync(0xffffffffu, ls_hi, 2);
    const float il = 1.f / ls_lo, ih = 1.f / ls_hi;

    // write ctx tf32-rounded, K-permuted for the out-proj GEMM
    const int r0 = my_qc * CHUNK_ + m0 + g;
#pragma unroll
    for (int nv = 0; nv < 8; nv++) {
        const int col = h * HD_ + nv * 8 + 2 * tq;
        const int p0 = perm_idx(col), p1 = perm_idx(col + 1);
        float* c0 = ctx + ((size_t)b * L_ + r0) * D_;
        float* c1 = ctx + ((size_t)b * L_ + r0 + 8) * D_;
        c0[p0] = f2tff(o[nv][0] * il); c0[p1] = f2tff(o[nv][1] * il);
        c1[p0] = f2tff(o[nv][2] * ih); c1[p1] = f2tff(o[nv][3] * ih);
    }
}

// ---------------------------------------------------------------------------
extern "C" void kernel_launch(void* const* d_in, const int* in_sizes, int n_in,
                              void* d_out, int out_size)
{
    const float* x    = (const float*)d_in[0];
    const float* Wqkv = (const float*)d_in[1];
    const float* bqkv = (const float*)d_in[2];
    const float* Wout = (const float*)d_in[3];
    const float* bout = (const float*)d_in[4];
    float* out = (float*)d_out;

    (void)in_sizes; (void)n_in; (void)out_size;

    cudaFuncSetAttribute(gemm_mma_kernel, cudaFuncAttributeMaxDynamicSharedMemorySize, GEMM_SMEM);
    cudaFuncSetAttribute(attn_mma_kernel, cudaFuncAttributeMaxDynamicSharedMemorySize, ATTN_SMEM);

    float *ctx_ptr, *xr, *wqkvr, *woutr;
    cudaGetSymbolAddress((void**)&ctx_ptr, g_ctx);
    cudaGetSymbolAddress((void**)&xr, g_xr);
    cudaGetSymbolAddress((void**)&wqkvr, g_wqkvr);
    cudaGetSymbolAddress((void**)&woutr, g_woutr);

    // 0. prep: round+permute x; transpose+round+permute weights
    {
        const int n8 = M_ROWS * D_ / 8;
        roundperm_kernel<<<(n8 + 255) / 256, 256>>>((const float4*)x, (float4*)xr, n8);
        dim3 blk(32, 8);
        transperm_kernel<<<dim3(QKV_N / 32, D_ / 32), blk>>>(Wqkv, wqkvr, D_, QKV_N);
        transperm_kernel<<<dim3(D_ / 32, D_ / 32), blk>>>(Wout, woutr, D_, D_);
    }
    // 1. QKV projection + scatter: q/k [bh][l][perm(d)], v [bh][d][l]
    {
        dim3 grid(QKV_N / 128, M_ROWS / 128);   // (24, 32)
        gemm_mma_kernel<<<grid, 256, GEMM_SMEM>>>(xr, wqkvr, bqkv, nullptr,
                                                  M_ROWS, QKV_N, D_, 1);
    }
    // 2. Block-causal attention -> g_ctx (permuted, tf32-rounded)
    //    1D grid: 8 chunk-pairs x 32 bh, heaviest pairs first
    {
        attn_mma_kernel<<<8 * 32, 512, ATTN_SMEM>>>(ctx_ptr);
    }
    // 3. Output projection -> d_out
    {
        dim3 grid(D_ / 128, M_ROWS / 128);      // (8, 32)
        gemm_mma_kernel<<<grid, 256, GEMM_SMEM>>>(ctx_ptr, woutr, bout, out,
                                                  M_ROWS, D_, D_, 0);
    }
}